// round 2
// baseline (speedup 1.0000x reference)
#include <cuda_runtime.h>
#include <stdint.h>

// ---------------- problem constants ----------------
#define BB 8
#define CC 128
#define HH 256
#define WW 256
#define OO 128
#define HWSZ (HH * WW)
#define NTHREADS 256

// padded row stride (floats) for both smem tiles: 132 => bank = 4*gid+tig (conflict-free)
#define STRD 132

// ---------------- smem layout (bytes) ----------------
#define SM_IFY 0
#define SM_IFX (SM_IFY + 512)
#define SM_W1  (SM_IFX + 512)
#define SM_W2  (SM_W1 + 512)
#define SM_W3  (SM_W2 + 512)
#define SM_W4  (SM_W3 + 512)
#define SM_A   4096                        // s tile: 128 x STRD floats
#define SM_B   (SM_A + 128 * STRD * 4)     // w_pw:   128 x STRD floats
#define SM_TOTAL (SM_B + 128 * STRD * 4)

__device__ __forceinline__ uint32_t f2tf32(float f) {
    uint32_t r;
    asm("cvt.rna.tf32.f32 %0, %1;" : "=r"(r) : "f"(f));
    return r;
}

__device__ __forceinline__ void mma8(float* d, const uint32_t* a, uint32_t b0, uint32_t b1) {
    asm volatile(
        "mma.sync.aligned.m16n8k8.row.col.f32.tf32.tf32.f32 "
        "{%0,%1,%2,%3}, {%4,%5,%6,%7}, {%8,%9}, {%0,%1,%2,%3};"
        : "+f"(d[0]), "+f"(d[1]), "+f"(d[2]), "+f"(d[3])
        : "r"(a[0]), "r"(a[1]), "r"(a[2]), "r"(a[3]), "r"(b0), "r"(b1));
}

__global__ void __launch_bounds__(NTHREADS, 1)
as2d_kernel(const float* __restrict__ x, const float* __restrict__ theta,
            const float* __restrict__ wdw, const float* __restrict__ wpw,
            float* __restrict__ out) {
    extern __shared__ char smem[];
    const int tid = threadIdx.x;
    const int wid = tid >> 5;
    const int lid = tid & 31;
    const int gid = lid >> 2;      // groupID (0..7)
    const int tig = lid & 3;       // threadID_in_group (0..3)

    // tile coords: 512 tiles per batch (256 rows x 2 half-rows of 128 pixels)
    const int blk = blockIdx.x;
    const int b = blk >> 9;
    const int rem = blk & 511;
    const int row = rem >> 1;
    const int j0 = (rem & 1) << 7;

    int*   ify = (int*)(smem + SM_IFY);
    int*   ifx = (int*)(smem + SM_IFX);
    float* W1 = (float*)(smem + SM_W1);
    float* W2 = (float*)(smem + SM_W2);
    float* W3 = (float*)(smem + SM_W3);
    float* W4 = (float*)(smem + SM_W4);
    float*    Asf = (float*)(smem + SM_A);
    uint32_t* Asu = (uint32_t*)(smem + SM_A);
    uint32_t* Bsu = (uint32_t*)(smem + SM_B);

    // ---- per-channel shift params (w_dw fused into the 4 bilinear weights) ----
    if (tid < CC) {
        float ty = -theta[2 * tid];
        float tx = -theta[2 * tid + 1];
        float fy = floorf(ty), fx = floorf(tx);
        float dy = ty - fy, dx = tx - fx;
        float wd = wdw[tid];
        ify[tid] = (int)fy;
        ifx[tid] = (int)fx;
        W1[tid] = (1.0f - dy) * (1.0f - dx) * wd;
        W2[tid] = (1.0f - dy) * dx * wd;
        W3[tid] = dy * (1.0f - dx) * wd;
        W4[tid] = dy * dx * wd;
    }

    // ---- load w_pw (N=O x K=C, row-major == col-major KxN for mma .col B) ----
    #pragma unroll
    for (int it = 0; it < 16; it++) {
        int q = tid + it * NTHREADS;           // float4 index, 4096 total
        int o = q >> 5;
        int c4 = (q & 31) << 2;
        float4 v = ((const float4*)wpw)[q];
        uint32_t* dst = Bsu + o * STRD + c4;
        dst[0] = f2tf32(v.x);
        dst[1] = f2tf32(v.y);
        dst[2] = f2tf32(v.z);
        dst[3] = f2tf32(v.w);
    }
    __syncthreads();

    // ---- gather: build s tile (M=128 pixels x K=128 channels) ----
    {
        const int p = tid & 127;
        const int j = j0 + p;
        const float* xb = x + (size_t)b * CC * HWSZ;
        const int cq0 = (tid >> 7) << 2;       // 0 or 4

        for (int c0 = cq0; c0 < CC; c0 += 8) {
            uint32_t vals[4];
            #pragma unroll
            for (int cc = 0; cc < 4; cc++) {
                int c = c0 + cc;
                int r0 = row + ify[c];
                int q0 = j + ifx[c];
                const float* base = xb + c * HWSZ;
                bool rok0 = (unsigned)r0 < (unsigned)HH;
                bool rok1 = (unsigned)(r0 + 1) < (unsigned)HH;
                bool cok0 = (unsigned)q0 < (unsigned)WW;
                bool cok1 = (unsigned)(q0 + 1) < (unsigned)WW;
                float v00 = (rok0 && cok0) ? base[r0 * WW + q0] : 0.0f;
                float v10 = (rok1 && cok0) ? base[(r0 + 1) * WW + q0] : 0.0f;
                // +1-column corners come from the next lane's loads
                float v01 = __shfl_down_sync(0xffffffffu, v00, 1);
                float v11 = __shfl_down_sync(0xffffffffu, v10, 1);
                if (lid == 31) {
                    v01 = (rok0 && cok1) ? base[r0 * WW + q0 + 1] : 0.0f;
                    v11 = (rok1 && cok1) ? base[(r0 + 1) * WW + q0 + 1] : 0.0f;
                }
                float s = v00 * W1[c] + v01 * W2[c] + v10 * W3[c] + v11 * W4[c];
                vals[cc] = f2tf32(s);
            }
            uint32_t* dst = Asu + p * STRD + c0;
            dst[0] = vals[0]; dst[1] = vals[1]; dst[2] = vals[2]; dst[3] = vals[3];
        }
    }
    __syncthreads();

    // ---- mainloop: D[p][o] = sum_c s[p][c] * w_pw[o][c] ----
    // 8 warps: wm = wid&3 -> 32-pixel chunk (2 m-tiles of 16), wn = wid>>2 -> 64-output chunk (8 n-tiles of 8)
    const int wm = wid & 3;
    const int wn = wid >> 2;
    float d[2][8][4] = {};
    {
        const int arow = wm * 32 + gid;
        const int bcol = wn * 64 + gid;
        #pragma unroll
        for (int k = 0; k < 16; k++) {
            int kb = k * 8 + tig;
            uint32_t a[2][4];
            #pragma unroll
            for (int mt = 0; mt < 2; mt++) {
                int rb = arow + mt * 16;
                a[mt][0] = Asu[rb * STRD + kb];
                a[mt][1] = Asu[(rb + 8) * STRD + kb];
                a[mt][2] = Asu[rb * STRD + kb + 4];
                a[mt][3] = Asu[(rb + 8) * STRD + kb + 4];
            }
            #pragma unroll
            for (int nt = 0; nt < 8; nt++) {
                uint32_t b0 = Bsu[(bcol + nt * 8) * STRD + kb];
                uint32_t b1 = Bsu[(bcol + nt * 8) * STRD + kb + 4];
                mma8(d[0][nt], a[0], b0, b1);
                mma8(d[1][nt], a[1], b0, b1);
            }
        }
    }
    __syncthreads();

    // ---- epilogue: bounce through smem (reuse A tile) as [o][p], then coalesced STG.128 ----
    {
        #pragma unroll
        for (int mt = 0; mt < 2; mt++) {
            #pragma unroll
            for (int nt = 0; nt < 8; nt++) {
                int ob = wn * 64 + nt * 8 + 2 * tig;
                int pb = wm * 32 + mt * 16 + gid;
                Asf[ob * STRD + pb]             = d[mt][nt][0];
                Asf[(ob + 1) * STRD + pb]       = d[mt][nt][1];
                Asf[ob * STRD + pb + 8]         = d[mt][nt][2];
                Asf[(ob + 1) * STRD + pb + 8]   = d[mt][nt][3];
            }
        }
    }
    __syncthreads();
    {
        float* ob = out + (size_t)b * OO * HWSZ + (size_t)row * WW + j0;
        #pragma unroll
        for (int oo = 0; oo < 16; oo++) {
            int o = wid * 16 + oo;
            float4 v = *(const float4*)(Asf + o * STRD + lid * 4);
            *(float4*)(ob + (size_t)o * HWSZ + lid * 4) = v;
        }
    }
}

extern "C" void kernel_launch(void* const* d_in, const int* in_sizes, int n_in,
                              void* d_out, int out_size) {
    (void)in_sizes; (void)n_in; (void)out_size;
    const float* x     = (const float*)d_in[0];
    const float* theta = (const float*)d_in[1];
    const float* wdw   = (const float*)d_in[2];
    const float* wpw   = (const float*)d_in[3];
    float* out = (float*)d_out;

    cudaFuncSetAttribute(as2d_kernel, cudaFuncAttributeMaxDynamicSharedMemorySize, SM_TOTAL);
    as2d_kernel<<<BB * (HH * WW / 128), NTHREADS, SM_TOTAL>>>(x, theta, wdw, wpw, out);
}

// round 3
// speedup vs baseline: 2.6756x; 2.6756x over previous
#include <cuda_runtime.h>
#include <stdint.h>

// ---------------- problem constants ----------------
#define BB 8
#define CC 128
#define HH 256
#define WW 256
#define OO 128
#define HWSZ (HH * WW)
#define NTHREADS 512

// padded row stride (floats): 132 => bank = (4*row + col) mod 32, conflict-free
#define STRD 132

// ---------------- smem layout (bytes) ----------------
#define SM_PW  0                            // float4 per channel: {W1,W2,W3,W4}  (2 KB)
#define SM_PI  2048                         // int2 per channel: {ify, ifx}       (1 KB)
#define SM_A   4096                         // s tile: 128 x STRD floats
#define SM_B   (SM_A + 128 * STRD * 4)      // w_pw:   128 x STRD floats
#define SM_TOTAL (SM_B + 128 * STRD * 4)

__device__ __forceinline__ uint32_t f2tf32(float f) {
    uint32_t r;
    asm("cvt.rna.tf32.f32 %0, %1;" : "=r"(r) : "f"(f));
    return r;
}

__device__ __forceinline__ void mma8(float* d, const uint32_t* a, uint32_t b0, uint32_t b1) {
    asm volatile(
        "mma.sync.aligned.m16n8k8.row.col.f32.tf32.tf32.f32 "
        "{%0,%1,%2,%3}, {%4,%5,%6,%7}, {%8,%9}, {%0,%1,%2,%3};"
        : "+f"(d[0]), "+f"(d[1]), "+f"(d[2]), "+f"(d[3])
        : "r"(a[0]), "r"(a[1]), "r"(a[2]), "r"(a[3]), "r"(b0), "r"(b1));
}

__global__ void __launch_bounds__(NTHREADS, 1)
as2d_kernel(const float* __restrict__ x, const float* __restrict__ theta,
            const float* __restrict__ wdw, const float* __restrict__ wpw,
            float* __restrict__ out) {
    extern __shared__ char smem[];
    const int tid = threadIdx.x;
    const int wid = tid >> 5;
    const int lid = tid & 31;
    const int gid = lid >> 2;      // groupID (0..7)
    const int tig = lid & 3;       // threadID_in_group (0..3)

    // tile coords: 512 tiles per batch (256 rows x 2 half-rows of 128 pixels)
    const int blk = blockIdx.x;
    const int b = blk >> 9;
    const int rem = blk & 511;
    const int row = rem >> 1;
    const int j0 = (rem & 1) << 7;

    float4* PW = (float4*)(smem + SM_PW);
    int2*   PI = (int2*)(smem + SM_PI);
    float*    Asf = (float*)(smem + SM_A);
    uint32_t* Asu = (uint32_t*)(smem + SM_A);
    uint32_t* Bsu = (uint32_t*)(smem + SM_B);

    // ---- per-channel shift params (w_dw fused into the 4 bilinear weights) ----
    if (tid < CC) {
        float ty = -theta[2 * tid];
        float tx = -theta[2 * tid + 1];
        float fy = floorf(ty), fx = floorf(tx);
        float dy = ty - fy, dx = tx - fx;
        float wd = wdw[tid];
        PI[tid] = make_int2((int)fy, (int)fx);
        PW[tid] = make_float4((1.0f - dy) * (1.0f - dx) * wd,
                              (1.0f - dy) * dx * wd,
                              dy * (1.0f - dx) * wd,
                              dy * dx * wd);
    }

    // ---- load w_pw (N=O x K=C row-major == col-major K x N for mma .col B) ----
    #pragma unroll
    for (int it = 0; it < 8; it++) {
        int q = tid + it * NTHREADS;           // float4 index, 4096 total
        int o = q >> 5;
        int c4 = (q & 31) << 2;
        float4 v = ((const float4*)wpw)[q];
        uint32_t* dst = Bsu + o * STRD + c4;
        dst[0] = f2tf32(v.x);
        dst[1] = f2tf32(v.y);
        dst[2] = f2tf32(v.z);
        dst[3] = f2tf32(v.w);
    }
    __syncthreads();

    // ---- gather: build s tile (M=128 pixels x K=128 channels) ----
    // 512 threads: p = tid&127 (pixel), cs = tid>>7 (channel quarter), 32 ch/thread
    {
        const int p = tid & 127;
        const int cs = tid >> 7;
        const int j = j0 + p;
        const float* xb = x + (size_t)b * CC * HWSZ;

        #pragma unroll
        for (int ch = 0; ch < 8; ch++) {
            const int c0 = cs * 32 + ch * 4;
            float v00[4], v10[4], w01[4], w11[4];
            float4 wv[4];
            bool rok0[4], rok1[4], cok1[4];
            int r0[4], q0[4];
            #pragma unroll
            for (int cc = 0; cc < 4; cc++) {
                int c = c0 + cc;
                int2 iv = PI[c];
                wv[cc] = PW[c];
                r0[cc] = row + iv.x;
                q0[cc] = j + iv.y;
                rok0[cc] = (unsigned)r0[cc] < (unsigned)HH;
                rok1[cc] = (unsigned)(r0[cc] + 1) < (unsigned)HH;
                bool cok0 = (unsigned)q0[cc] < (unsigned)WW;
                cok1[cc] = (unsigned)(q0[cc] + 1) < (unsigned)WW;
                const float* base = xb + c * HWSZ;
                v00[cc] = (rok0[cc] && cok0) ? base[r0[cc] * WW + q0[cc]] : 0.0f;
                v10[cc] = (rok1[cc] && cok0) ? base[(r0[cc] + 1) * WW + q0[cc]] : 0.0f;
            }
            uint32_t vals[4];
            #pragma unroll
            for (int cc = 0; cc < 4; cc++) {
                float v01 = __shfl_down_sync(0xffffffffu, v00[cc], 1);
                float v11 = __shfl_down_sync(0xffffffffu, v10[cc], 1);
                if (lid == 31) {
                    const float* base = xb + (c0 + cc) * HWSZ;
                    v01 = (rok0[cc] && cok1[cc]) ? base[r0[cc] * WW + q0[cc] + 1] : 0.0f;
                    v11 = (rok1[cc] && cok1[cc]) ? base[(r0[cc] + 1) * WW + q0[cc] + 1] : 0.0f;
                }
                float s = v00[cc] * wv[cc].x + v01 * wv[cc].y + v10[cc] * wv[cc].z + v11 * wv[cc].w;
                vals[cc] = f2tf32(s);
            }
            uint32_t* dst = Asu + p * STRD + c0;
            dst[0] = vals[0]; dst[1] = vals[1]; dst[2] = vals[2]; dst[3] = vals[3];
        }
    }
    __syncthreads();

    // ---- mainloop: D[p][o] = sum_c s[p][c] * w_pw[o][c] ----
    // 16 warps, warp tile 32(m) x 32(n): wm = wid&3, wn = wid>>2
    const int wm = wid & 3;
    const int wn = wid >> 2;
    float d[2][4][4] = {};
    {
        const int arow = wm * 32 + gid;
        const int bcol = wn * 32 + gid;
        #pragma unroll
        for (int k = 0; k < 16; k++) {
            int kb = k * 8 + tig;
            uint32_t a[2][4];
            #pragma unroll
            for (int mt = 0; mt < 2; mt++) {
                int rb = arow + mt * 16;
                a[mt][0] = Asu[rb * STRD + kb];
                a[mt][1] = Asu[(rb + 8) * STRD + kb];
                a[mt][2] = Asu[rb * STRD + kb + 4];
                a[mt][3] = Asu[(rb + 8) * STRD + kb + 4];
            }
            #pragma unroll
            for (int nt = 0; nt < 4; nt++) {
                uint32_t b0 = Bsu[(bcol + nt * 8) * STRD + kb];
                uint32_t b1 = Bsu[(bcol + nt * 8) * STRD + kb + 4];
                mma8(d[0][nt], a[0], b0, b1);
                mma8(d[1][nt], a[1], b0, b1);
            }
        }
    }
    __syncthreads();

    // ---- epilogue: bounce through smem (reuse A tile) as [o][p], then coalesced STG.128 ----
    {
        #pragma unroll
        for (int mt = 0; mt < 2; mt++) {
            #pragma unroll
            for (int nt = 0; nt < 4; nt++) {
                int ob = wn * 32 + nt * 8 + 2 * tig;
                int pb = wm * 32 + mt * 16 + gid;
                Asf[ob * STRD + pb]             = d[mt][nt][0];
                Asf[(ob + 1) * STRD + pb]       = d[mt][nt][1];
                Asf[ob * STRD + pb + 8]         = d[mt][nt][2];
                Asf[(ob + 1) * STRD + pb + 8]   = d[mt][nt][3];
            }
        }
    }
    __syncthreads();
    {
        float* ob = out + (size_t)b * OO * HWSZ + (size_t)row * WW + j0;
        #pragma unroll
        for (int oo = 0; oo < 8; oo++) {
            int o = wid * 8 + oo;
            float4 v = *(const float4*)(Asf + o * STRD + lid * 4);
            *(float4*)(ob + (size_t)o * HWSZ + lid * 4) = v;
        }
    }
}

extern "C" void kernel_launch(void* const* d_in, const int* in_sizes, int n_in,
                              void* d_out, int out_size) {
    (void)in_sizes; (void)n_in; (void)out_size;
    const float* x     = (const float*)d_in[0];
    const float* theta = (const float*)d_in[1];
    const float* wdw   = (const float*)d_in[2];
    const float* wpw   = (const float*)d_in[3];
    float* out = (float*)d_out;

    cudaFuncSetAttribute(as2d_kernel, cudaFuncAttributeMaxDynamicSharedMemorySize, SM_TOTAL);
    as2d_kernel<<<BB * (HH * WW / 128), NTHREADS, SM_TOTAL>>>(x, theta, wdw, wpw, out);
}

// round 4
// speedup vs baseline: 2.9852x; 1.1157x over previous
#include <cuda_runtime.h>
#include <stdint.h>

// ---------------- problem constants ----------------
#define BB 8
#define CC 128
#define HH 256
#define WW 256
#define OO 128
#define HWSZ (HH * WW)
#define NTHREADS 512
#define MPIX 64            // pixels per CTA tile (MMA M)

// padded row stride (floats): 132 => conflict-free banks for mma fragment LDS
#define STRD 132
// epilogue bounce stride
#define ESTRD 68

// ---------------- smem layout (bytes) ----------------
#define SM_PW  0                            // float4 per channel: {W1,W2,W3,W4}  (2 KB)
#define SM_PI  2048                         // int2 per channel: {ify, ifx}       (1 KB)
#define SM_A   4096                         // s tile: 64 x STRD floats (33 KB)
#define SM_B   (SM_A + MPIX * STRD * 4)     // w_pw: 128 x STRD floats (66 KB)
#define SM_TOTAL (SM_B + 128 * STRD * 4)    // 105472 bytes -> 2 CTAs/SM

__device__ __forceinline__ uint32_t f2tf32(float f) {
    uint32_t r;
    asm("cvt.rna.tf32.f32 %0, %1;" : "=r"(r) : "f"(f));
    return r;
}

__device__ __forceinline__ void mma8(float* d, const uint32_t* a, uint32_t b0, uint32_t b1) {
    asm volatile(
        "mma.sync.aligned.m16n8k8.row.col.f32.tf32.tf32.f32 "
        "{%0,%1,%2,%3}, {%4,%5,%6,%7}, {%8,%9}, {%0,%1,%2,%3};"
        : "+f"(d[0]), "+f"(d[1]), "+f"(d[2]), "+f"(d[3])
        : "r"(a[0]), "r"(a[1]), "r"(a[2]), "r"(a[3]), "r"(b0), "r"(b1));
}

__global__ void __launch_bounds__(NTHREADS, 2)
as2d_kernel(const float* __restrict__ x, const float* __restrict__ theta,
            const float* __restrict__ wdw, const float* __restrict__ wpw,
            float* __restrict__ out) {
    extern __shared__ char smem[];
    const int tid = threadIdx.x;
    const int wid = tid >> 5;
    const int lid = tid & 31;
    const int gid = lid >> 2;      // groupID (0..7)
    const int tig = lid & 3;       // threadID_in_group (0..3)

    // tile coords: 1024 tiles per batch (256 rows x 4 quarter-rows of 64 pixels)
    const int blk = blockIdx.x;
    const int b = blk >> 10;
    const int rem = blk & 1023;
    const int row = rem >> 2;
    const int j0 = (rem & 3) << 6;

    float4* PW = (float4*)(smem + SM_PW);
    int2*   PI = (int2*)(smem + SM_PI);
    float*    Esf = (float*)smem;            // epilogue bounce, overlays params+A
    uint32_t* Asu = (uint32_t*)(smem + SM_A);
    uint32_t* Bsu = (uint32_t*)(smem + SM_B);

    // ---- per-channel shift params (w_dw fused into the 4 bilinear weights) ----
    if (tid < CC) {
        float ty = -theta[2 * tid];
        float tx = -theta[2 * tid + 1];
        float fy = floorf(ty), fx = floorf(tx);
        float dy = ty - fy, dx = tx - fx;
        float wd = wdw[tid];
        PI[tid] = make_int2((int)fy, (int)fx);
        PW[tid] = make_float4((1.0f - dy) * (1.0f - dx) * wd,
                              (1.0f - dy) * dx * wd,
                              dy * (1.0f - dx) * wd,
                              dy * dx * wd);
    }

    // ---- load w_pw (N=O x K=C row-major == col-major K x N for mma .col B) ----
    #pragma unroll
    for (int it = 0; it < 8; it++) {
        int q = tid + it * NTHREADS;           // float4 index, 4096 total
        int o = q >> 5;
        int c4 = (q & 31) << 2;
        float4 v = ((const float4*)wpw)[q];
        uint32_t* dst = Bsu + o * STRD + c4;
        dst[0] = f2tf32(v.x);
        dst[1] = f2tf32(v.y);
        dst[2] = f2tf32(v.z);
        dst[3] = f2tf32(v.w);
    }
    __syncthreads();

    // ---- gather: build s tile (M=64 pixels x K=128 channels) ----
    // p = (wid&1)*32 + lid (consecutive within warp), cs = tid>>6 -> 16 ch/thread
    {
        const int p = (tid & 63);
        const int cs = tid >> 6;
        const int j = j0 + p;
        const float* xb = x + (size_t)b * CC * HWSZ;

        #pragma unroll
        for (int ch = 0; ch < 4; ch++) {
            const int c0 = cs * 16 + ch * 4;
            float v00[4], v10[4];
            float4 wv[4];
            bool rok0[4], rok1[4], cok1[4];
            int r0[4], q0[4];
            #pragma unroll
            for (int cc = 0; cc < 4; cc++) {
                int c = c0 + cc;
                int2 iv = PI[c];
                wv[cc] = PW[c];
                r0[cc] = row + iv.x;
                q0[cc] = j + iv.y;
                rok0[cc] = (unsigned)r0[cc] < (unsigned)HH;
                rok1[cc] = (unsigned)(r0[cc] + 1) < (unsigned)HH;
                bool cok0 = (unsigned)q0[cc] < (unsigned)WW;
                cok1[cc] = (unsigned)(q0[cc] + 1) < (unsigned)WW;
                const float* base = xb + c * HWSZ;
                v00[cc] = (rok0[cc] && cok0) ? base[r0[cc] * WW + q0[cc]] : 0.0f;
                v10[cc] = (rok1[cc] && cok0) ? base[(r0[cc] + 1) * WW + q0[cc]] : 0.0f;
            }
            uint32_t vals[4];
            #pragma unroll
            for (int cc = 0; cc < 4; cc++) {
                float v01 = __shfl_down_sync(0xffffffffu, v00[cc], 1);
                float v11 = __shfl_down_sync(0xffffffffu, v10[cc], 1);
                if (lid == 31) {
                    const float* base = xb + (c0 + cc) * HWSZ;
                    v01 = (rok0[cc] && cok1[cc]) ? base[r0[cc] * WW + q0[cc] + 1] : 0.0f;
                    v11 = (rok1[cc] && cok1[cc]) ? base[(r0[cc] + 1) * WW + q0[cc] + 1] : 0.0f;
                }
                float s = v00[cc] * wv[cc].x + v01 * wv[cc].y + v10[cc] * wv[cc].z + v11 * wv[cc].w;
                vals[cc] = f2tf32(s);
            }
            uint32_t* dst = Asu + p * STRD + c0;
            dst[0] = vals[0]; dst[1] = vals[1]; dst[2] = vals[2]; dst[3] = vals[3];
        }
    }
    __syncthreads();

    // ---- mainloop: D[p][o] = sum_c s[p][c] * w_pw[o][c] ----
    // 16 warps, warp tile 16(m) x 32(n): wm = wid&3, wn = wid>>2
    const int wm = wid & 3;
    const int wn = wid >> 2;
    float d[4][4] = {};
    {
        const int arow = wm * 16 + gid;
        const int bcol = wn * 32 + gid;
        #pragma unroll
        for (int k = 0; k < 16; k++) {
            int kb = k * 8 + tig;
            uint32_t a[4];
            a[0] = Asu[arow * STRD + kb];
            a[1] = Asu[(arow + 8) * STRD + kb];
            a[2] = Asu[arow * STRD + kb + 4];
            a[3] = Asu[(arow + 8) * STRD + kb + 4];
            #pragma unroll
            for (int nt = 0; nt < 4; nt++) {
                uint32_t b0 = Bsu[(bcol + nt * 8) * STRD + kb];
                uint32_t b1 = Bsu[(bcol + nt * 8) * STRD + kb + 4];
                mma8(d[nt], a, b0, b1);
            }
        }
    }
    __syncthreads();

    // ---- epilogue: bounce through smem as [o][p] (overlays params+A), coalesced STG.128 ----
    {
        #pragma unroll
        for (int nt = 0; nt < 4; nt++) {
            int ob = wn * 32 + nt * 8 + 2 * tig;
            int pb = wm * 16 + gid;
            Esf[ob * ESTRD + pb]           = d[nt][0];
            Esf[(ob + 1) * ESTRD + pb]     = d[nt][1];
            Esf[ob * ESTRD + pb + 8]       = d[nt][2];
            Esf[(ob + 1) * ESTRD + pb + 8] = d[nt][3];
        }
    }
    __syncthreads();
    {
        float* ob = out + (size_t)b * OO * HWSZ + (size_t)row * WW + j0;
        const int orow = tid >> 4;          // 0..31
        const int l4 = tid & 15;            // float4 index within 64-pixel row
        #pragma unroll
        for (int oo = 0; oo < 4; oo++) {
            int o = oo * 32 + orow;
            float4 v = *(const float4*)(Esf + o * ESTRD + l4 * 4);
            *(float4*)(ob + (size_t)o * HWSZ + l4 * 4) = v;
        }
    }
}

extern "C" void kernel_launch(void* const* d_in, const int* in_sizes, int n_in,
                              void* d_out, int out_size) {
    (void)in_sizes; (void)n_in; (void)out_size;
    const float* x     = (const float*)d_in[0];
    const float* theta = (const float*)d_in[1];
    const float* wdw   = (const float*)d_in[2];
    const float* wpw   = (const float*)d_in[3];
    float* out = (float*)d_out;

    cudaFuncSetAttribute(as2d_kernel, cudaFuncAttributeMaxDynamicSharedMemorySize, SM_TOTAL);
    as2d_kernel<<<BB * (HH * WW / MPIX), NTHREADS, SM_TOTAL>>>(x, theta, wdw, wpw, out);
}

// round 5
// speedup vs baseline: 3.9202x; 1.3132x over previous
#include <cuda_runtime.h>
#include <cuda_fp16.h>
#include <stdint.h>

// ---------------- problem constants ----------------
#define BB 8
#define CC 128
#define HH 256
#define WW 256
#define OO 128
#define HWSZ (HH * WW)
#define NTHREADS 512
#define MPIX 64            // pixels per CTA tile (MMA M)

// A/B smem tiles: rows of 64 h2-words padded to 72 (bank-friendly: 72 mod 32 = 8)
#define RWRD 72
// epilogue bounce stride (floats)
#define ESTRD 68

// ---------------- smem layout (bytes) ----------------
#define SM_A   0                             // A: 64 x RWRD uint32 (18432 B)
#define SM_B   (MPIX * RWRD * 4)             // B: 128 x RWRD uint32 (36864 B)
#define SM_P   (SM_B + 128 * RWRD * 4)       // params: PW float4[128], PI int2[128]
#define SM_PI  (SM_P + 2048)
#define SM_TOTAL (SM_PI + 1024)              // 58368 B -> 2 CTAs/SM

// ---------------- precomputed globals (written by prep kernel) ----------------
__device__ float4   g_PW[CC];
__device__ int2     g_PI[CC];
__device__ uint32_t g_Bw[OO * 64];           // fp16x2 w_pw, pair-interleaved words

// pair-interleave: words w and w+4 adjacent (for LDS.64 fragment loads)
__host__ __device__ __forceinline__ int pairpos(int w) {
    return (w & ~7) + ((w & 3) << 1) + ((w >> 2) & 1);
}

__device__ __forceinline__ uint32_t packh2(float lo, float hi) {
    __half2 h = __floats2half2_rn(lo, hi);
    return *(uint32_t*)&h;
}

__device__ __forceinline__ void mma16(float* d, uint32_t a0, uint32_t a1, uint32_t a2,
                                      uint32_t a3, uint32_t b0, uint32_t b1) {
    asm volatile(
        "mma.sync.aligned.m16n8k16.row.col.f32.f16.f16.f32 "
        "{%0,%1,%2,%3}, {%4,%5,%6,%7}, {%8,%9}, {%0,%1,%2,%3};"
        : "+f"(d[0]), "+f"(d[1]), "+f"(d[2]), "+f"(d[3])
        : "r"(a0), "r"(a1), "r"(a2), "r"(a3), "r"(b0), "r"(b1));
}

// ---------------- prep kernel: params + fp16 pre-layout of w_pw ----------------
__global__ void prep_kernel(const float* __restrict__ theta, const float* __restrict__ wdw,
                            const float* __restrict__ wpw) {
    int t = blockIdx.x * blockDim.x + threadIdx.x;
    if (t < CC) {
        float ty = -theta[2 * t];
        float tx = -theta[2 * t + 1];
        float fy = floorf(ty), fx = floorf(tx);
        float dy = ty - fy, dx = tx - fx;
        float wd = wdw[t];
        g_PI[t] = make_int2((int)fy, (int)fx);
        g_PW[t] = make_float4((1.0f - dy) * (1.0f - dx) * wd,
                              (1.0f - dy) * dx * wd,
                              dy * (1.0f - dx) * wd,
                              dy * dx * wd);
    }
    if (t < OO * CC / 4) {                 // 4096 float4 chunks
        int o = t >> 5;
        int c4 = (t & 31) << 2;            // first channel of the chunk
        float4 v = ((const float4*)wpw)[t];
        int w0 = c4 >> 1;                  // even word index
        int p0 = pairpos(w0);
        g_Bw[o * 64 + p0]     = packh2(v.x, v.y);
        g_Bw[o * 64 + p0 + 2] = packh2(v.z, v.w);
    }
}

// ---------------- main kernel ----------------
__global__ void __launch_bounds__(NTHREADS, 2)
as2d_kernel(const float* __restrict__ x, float* __restrict__ out) {
    extern __shared__ char smem[];
    const int tid = threadIdx.x;
    const int wid = tid >> 5;
    const int lid = tid & 31;
    const int gid = lid >> 2;      // groupID (0..7)
    const int tig = lid & 3;       // threadID_in_group (0..3)

    // tile coords: 1024 tiles per batch (256 rows x 4 quarter-rows of 64 pixels)
    const int blk = blockIdx.x;
    const int b = blk >> 10;
    const int rem = blk & 1023;
    const int row = rem >> 2;
    const int j0 = (rem & 3) << 6;

    uint32_t* Asw = (uint32_t*)(smem + SM_A);
    uint32_t* Bsw = (uint32_t*)(smem + SM_B);
    float4*   PW  = (float4*)(smem + SM_P);
    int2*     PI  = (int2*)(smem + SM_PI);
    float*    Esf = (float*)smem;            // epilogue bounce, overlays A+B

    // ---- stage params + B tile into smem ----
    if (tid < CC) {
        PW[tid] = g_PW[tid];
        PI[tid] = g_PI[tid];
    }
    #pragma unroll
    for (int i = 0; i < 4; i++) {
        int w4 = tid + i * NTHREADS;         // uint4 chunk index (0..2047)
        int r = w4 >> 4;
        int pos = (w4 & 15) << 2;
        uint4 v = ((const uint4*)g_Bw)[w4];
        *(uint4*)(Bsw + r * RWRD + pos) = v;
    }
    __syncthreads();

    // ---- gather: build s tile (M=64 pixels x K=128 channels, fp16) ----
    {
        const int p = tid & 63;
        const int cs = tid >> 6;             // 0..7 -> 16 channels each
        const int j = j0 + p;
        const float* xb = x + (size_t)b * CC * HWSZ;
        const int sg = ((p >> 2) & 7) << 1;  // A-tile XOR bank swizzle

        #pragma unroll
        for (int ch = 0; ch < 4; ch++) {
            const int c0 = cs * 16 + ch * 4;
            float v00[4], v10[4];
            float4 wv[4];
            bool rok0[4], rok1[4], cok1[4];
            int r0[4], q0[4];
            #pragma unroll
            for (int cc = 0; cc < 4; cc++) {
                int c = c0 + cc;
                int2 iv = PI[c];
                wv[cc] = PW[c];
                r0[cc] = row + iv.x;
                q0[cc] = j + iv.y;
                rok0[cc] = (unsigned)r0[cc] < (unsigned)HH;
                rok1[cc] = (unsigned)(r0[cc] + 1) < (unsigned)HH;
                bool cok0 = (unsigned)q0[cc] < (unsigned)WW;
                cok1[cc] = (unsigned)(q0[cc] + 1) < (unsigned)WW;
                const float* base = xb + c * HWSZ;
                v00[cc] = (rok0[cc] && cok0) ? base[r0[cc] * WW + q0[cc]] : 0.0f;
                v10[cc] = (rok1[cc] && cok0) ? base[(r0[cc] + 1) * WW + q0[cc]] : 0.0f;
            }
            float s[4];
            #pragma unroll
            for (int cc = 0; cc < 4; cc++) {
                float v01 = __shfl_down_sync(0xffffffffu, v00[cc], 1);
                float v11 = __shfl_down_sync(0xffffffffu, v10[cc], 1);
                if (lid == 31) {
                    const float* base = xb + (c0 + cc) * HWSZ;
                    v01 = (rok0[cc] && cok1[cc]) ? base[r0[cc] * WW + q0[cc] + 1] : 0.0f;
                    v11 = (rok1[cc] && cok1[cc]) ? base[(r0[cc] + 1) * WW + q0[cc] + 1] : 0.0f;
                }
                s[cc] = v00[cc] * wv[cc].x + v01 * wv[cc].y + v10[cc] * wv[cc].z + v11 * wv[cc].w;
            }
            // words w0 = c0>>1 (channels c0,c0+1), w0+1 (c0+2,c0+3)
            int pw0 = pairpos(c0 >> 1);
            Asw[p * RWRD + (pw0 ^ sg)]       = packh2(s[0], s[1]);
            Asw[p * RWRD + ((pw0 + 2) ^ sg)] = packh2(s[2], s[3]);
        }
    }
    __syncthreads();

    // ---- mainloop: D[p][o] = sum_c s[p][c] * w_pw[o][c], fp16 MMA k16 x 8 ----
    const int wm = wid & 3;
    const int wn = wid >> 2;
    float d[4][4] = {};
    {
        const int r1 = wm * 16 + gid;
        const int r2 = r1 + 8;
        const int sg1 = ((r1 >> 2) & 7) << 1;
        const int sg2 = ((r2 >> 2) & 7) << 1;
        const uint32_t* A1 = Asw + r1 * RWRD;
        const uint32_t* A2 = Asw + r2 * RWRD;
        const uint32_t* Bb = Bsw + (wn * 32 + gid) * RWRD + 2 * tig;
        #pragma unroll
        for (int k = 0; k < 8; k++) {
            int t2 = 8 * k + 2 * tig;
            uint2 aA = *(const uint2*)(A1 + (t2 ^ sg1));   // {a0a1, a4a5}
            uint2 aB = *(const uint2*)(A2 + (t2 ^ sg2));   // {a2a3, a6a7}
            #pragma unroll
            for (int nt = 0; nt < 4; nt++) {
                uint2 bv = *(const uint2*)(Bb + nt * 8 * RWRD + 8 * k);
                mma16(d[nt], aA.x, aB.x, aA.y, aB.y, bv.x, bv.y);
            }
        }
    }
    __syncthreads();

    // ---- epilogue: bounce through smem as [o][p], coalesced STG.128 ----
    {
        #pragma unroll
        for (int nt = 0; nt < 4; nt++) {
            int ob = wn * 32 + nt * 8 + 2 * tig;
            int pb = wm * 16 + gid;
            Esf[ob * ESTRD + pb]           = d[nt][0];
            Esf[(ob + 1) * ESTRD + pb]     = d[nt][1];
            Esf[ob * ESTRD + pb + 8]       = d[nt][2];
            Esf[(ob + 1) * ESTRD + pb + 8] = d[nt][3];
        }
    }
    __syncthreads();
    {
        float* ob = out + (size_t)b * OO * HWSZ + (size_t)row * WW + j0;
        const int orow = tid >> 4;          // 0..31
        const int l4 = tid & 15;            // float4 index within 64-pixel row
        #pragma unroll
        for (int oo = 0; oo < 4; oo++) {
            int o = oo * 32 + orow;
            float4 v = *(const float4*)(Esf + o * ESTRD + l4 * 4);
            *(float4*)(ob + (size_t)o * HWSZ + l4 * 4) = v;
        }
    }
}

extern "C" void kernel_launch(void* const* d_in, const int* in_sizes, int n_in,
                              void* d_out, int out_size) {
    (void)in_sizes; (void)n_in; (void)out_size;
    const float* x     = (const float*)d_in[0];
    const float* theta = (const float*)d_in[1];
    const float* wdw   = (const float*)d_in[2];
    const float* wpw   = (const float*)d_in[3];
    float* out = (float*)d_out;

    prep_kernel<<<8, 512>>>(theta, wdw, wpw);
    cudaFuncSetAttribute(as2d_kernel, cudaFuncAttributeMaxDynamicSharedMemorySize, SM_TOTAL);
    as2d_kernel<<<BB * (HH * WW / MPIX), NTHREADS, SM_TOTAL>>>(x, out);
}

// round 9
// speedup vs baseline: 4.7779x; 1.2188x over previous
#include <cuda_runtime.h>
#include <cuda_fp16.h>
#include <stdint.h>

// ---------------- problem constants ----------------
#define BB 8
#define CC 128
#define HH 256
#define WW 256
#define OO 128
#define HWSZ (HH * WW)
#define NTHREADS 512
#define MPIX 64            // pixels per CTA tile (MMA M)

// A/B smem tiles: rows of 64 h2-words padded to 72 (bank-friendly: 72 mod 32 = 8)
#define RWRD 72
// epilogue bounce stride (floats)
#define ESTRD 68

// ---------------- smem layout (bytes) ----------------
#define SM_A   0                             // A: 64 x RWRD uint32 (18432 B)
#define SM_B   (MPIX * RWRD * 4)             // B: 128 x RWRD uint32 (36864 B)
#define SM_W   (SM_B + 128 * RWRD * 4)       // row-masked weights float4[128]
#define SM_O   (SM_W + 2048)                 // int4 per channel {off0, off1, ifx, -}
#define SM_TOTAL (SM_O + 2048)               // 59392 B -> 2 CTAs/SM

// ---------------- precomputed globals (written by prep kernel) ----------------
__device__ float4   g_PW[CC];
__device__ int2     g_PI[CC];
__device__ uint32_t g_Bw[OO * 64];           // fp16x2 w_pw, pair-interleaved words

// pair-interleave: words w and w+4 adjacent (for LDS.64 fragment loads)
__host__ __device__ __forceinline__ int pairpos(int w) {
    return (w & ~7) + ((w & 3) << 1) + ((w >> 2) & 1);
}

__device__ __forceinline__ uint32_t packh2(float lo, float hi) {
    __half2 h = __floats2half2_rn(lo, hi);
    return *(uint32_t*)&h;
}

__device__ __forceinline__ void mma16(float* d, uint32_t a0, uint32_t a1, uint32_t a2,
                                      uint32_t a3, uint32_t b0, uint32_t b1) {
    asm volatile(
        "mma.sync.aligned.m16n8k16.row.col.f32.f16.f16.f32 "
        "{%0,%1,%2,%3}, {%4,%5,%6,%7}, {%8,%9}, {%0,%1,%2,%3};"
        : "+f"(d[0]), "+f"(d[1]), "+f"(d[2]), "+f"(d[3])
        : "r"(a0), "r"(a1), "r"(a2), "r"(a3), "r"(b0), "r"(b1));
}

// ---------------- prep kernel: params + fp16 pre-layout of w_pw ----------------
__global__ void prep_kernel(const float* __restrict__ theta, const float* __restrict__ wdw,
                            const float* __restrict__ wpw) {
    int t = blockIdx.x * blockDim.x + threadIdx.x;
    if (t < CC) {
        float ty = -theta[2 * t];
        float tx = -theta[2 * t + 1];
        float fy = floorf(ty), fx = floorf(tx);
        float dy = ty - fy, dx = tx - fx;
        float wd = wdw[t];
        g_PI[t] = make_int2((int)fy, (int)fx);
        g_PW[t] = make_float4((1.0f - dy) * (1.0f - dx) * wd,
                              (1.0f - dy) * dx * wd,
                              dy * (1.0f - dx) * wd,
                              dy * dx * wd);
    }
    if (t < OO * CC / 4) {                 // 4096 float4 chunks
        int o = t >> 5;
        int c4 = (t & 31) << 2;            // first channel of the chunk
        float4 v = ((const float4*)wpw)[t];
        int w0 = c4 >> 1;                  // even word index
        int p0 = pairpos(w0);
        g_Bw[o * 64 + p0]     = packh2(v.x, v.y);
        g_Bw[o * 64 + p0 + 2] = packh2(v.z, v.w);
    }
}

// ---------------- main kernel ----------------
__global__ void __launch_bounds__(NTHREADS, 2)
as2d_kernel(const float* __restrict__ x, float* __restrict__ out) {
    extern __shared__ char smem[];
    const int tid = threadIdx.x;
    const int wid = tid >> 5;
    const int lid = tid & 31;
    const int gid = lid >> 2;      // groupID (0..7)
    const int tig = lid & 3;       // threadID_in_group (0..3)

    // tile coords: 1024 tiles per batch (256 rows x 4 quarter-rows of 64 pixels)
    const int blk = blockIdx.x;
    const int b = blk >> 10;
    const int rem = blk & 1023;
    const int row = rem >> 2;
    const int j0 = (rem & 3) << 6;

    uint32_t* Asw = (uint32_t*)(smem + SM_A);
    uint32_t* Bsw = (uint32_t*)(smem + SM_B);
    float4*   SW  = (float4*)(smem + SM_W);
    int4*     SO  = (int4*)(smem + SM_O);
    float*    Esf = (float*)smem;            // epilogue bounce, overlays A+B

    // ---- per-CTA setup: fold row validity into weights, clamp rows into offsets ----
    if (tid < CC) {
        int2 iv = g_PI[tid];
        float4 w = g_PW[tid];
        int r0 = row + iv.x;
        int r1 = r0 + 1;
        bool rok0 = (unsigned)r0 < (unsigned)HH;
        bool rok1 = (unsigned)r1 < (unsigned)HH;
        int cr0 = min(max(r0, 0), HH - 1);
        int cr1 = min(max(r1, 0), HH - 1);
        SW[tid] = make_float4(rok0 ? w.x : 0.0f, rok0 ? w.y : 0.0f,
                              rok1 ? w.z : 0.0f, rok1 ? w.w : 0.0f);
        SO[tid] = make_int4(cr0 * WW + iv.y, cr1 * WW + iv.y, iv.y, 0);
    }
    // ---- stage B tile into smem (pure copy, already fp16+interleaved) ----
    #pragma unroll
    for (int i = 0; i < 4; i++) {
        int w4 = tid + i * NTHREADS;         // uint4 chunk index (0..2047)
        int r = w4 >> 4;
        int pos = (w4 & 15) << 2;
        uint4 v = ((const uint4*)g_Bw)[w4];
        *(uint4*)(Bsw + r * RWRD + pos) = v;
    }
    __syncthreads();

    // ---- gather: build s tile (M=64 pixels x K=128 channels, fp16) ----
    {
        const int p = tid & 63;
        const int cs = tid >> 6;             // 0..7 -> 16 channels each
        const int j = j0 + p;
        const float* xbj = x + (size_t)b * CC * HWSZ + j;
        const int sg = ((p >> 2) & 7) << 1;  // A-tile XOR bank swizzle
        uint32_t* Ath = Asw + p * RWRD;

        if (j0 == 64 || j0 == 128) {
            // fast path: columns provably in-bounds, rows folded -> zero predicates
            #pragma unroll
            for (int ch = 0; ch < 4; ch++) {
                const int c0 = cs * 16 + ch * 4;
                float s[4];
                #pragma unroll
                for (int cc = 0; cc < 4; cc++) {
                    int c = c0 + cc;
                    int4 off = SO[c];
                    float4 wv = SW[c];
                    const float* a0 = xbj + (size_t)c * HWSZ + off.x;
                    const float* a1 = xbj + (size_t)c * HWSZ + off.y;
                    float v00 = a0[0], v01 = a0[1];
                    float v10 = a1[0], v11 = a1[1];
                    s[cc] = v00 * wv.x + v01 * wv.y + v10 * wv.z + v11 * wv.w;
                }
                int pw0 = pairpos(c0 >> 1);
                Ath[pw0 ^ sg]       = packh2(s[0], s[1]);
                Ath[(pw0 + 2) ^ sg] = packh2(s[2], s[3]);
            }
        } else {
            // boundary path: column predicates (rows still folded)
            #pragma unroll
            for (int ch = 0; ch < 4; ch++) {
                const int c0 = cs * 16 + ch * 4;
                float s[4];
                #pragma unroll
                for (int cc = 0; cc < 4; cc++) {
                    int c = c0 + cc;
                    int4 off = SO[c];
                    float4 wv = SW[c];
                    int q0 = j + off.z;
                    bool cok0 = (unsigned)q0 < (unsigned)WW;
                    bool cok1 = (unsigned)(q0 + 1) < (unsigned)WW;
                    const float* a0 = xbj + (size_t)c * HWSZ + off.x;
                    const float* a1 = xbj + (size_t)c * HWSZ + off.y;
                    float v00 = cok0 ? a0[0] : 0.0f;
                    float v01 = cok1 ? a0[1] : 0.0f;
                    float v10 = cok0 ? a1[0] : 0.0f;
                    float v11 = cok1 ? a1[1] : 0.0f;
                    s[cc] = v00 * wv.x + v01 * wv.y + v10 * wv.z + v11 * wv.w;
                }
                int pw0 = pairpos(c0 >> 1);
                Ath[pw0 ^ sg]       = packh2(s[0], s[1]);
                Ath[(pw0 + 2) ^ sg] = packh2(s[2], s[3]);
            }
        }
    }
    __syncthreads();

    // ---- mainloop: D[p][o] = sum_c s[p][c] * w_pw[o][c], fp16 MMA k16 x 8 ----
    const int wm = wid & 3;
    const int wn = wid >> 2;
    float d[4][4] = {};
    {
        const int r1 = wm * 16 + gid;
        const int r2 = r1 + 8;
        const int sg1 = ((r1 >> 2) & 7) << 1;
        const int sg2 = ((r2 >> 2) & 7) << 1;
        const uint32_t* A1 = Asw + r1 * RWRD;
        const uint32_t* A2 = Asw + r2 * RWRD;
        const uint32_t* Bb = Bsw + (wn * 32 + gid) * RWRD + 2 * tig;
        #pragma unroll
        for (int k = 0; k < 8; k++) {
            int t2 = 8 * k + 2 * tig;
            uint2 aA = *(const uint2*)(A1 + (t2 ^ sg1));   // {a0a1, a4a5}
            uint2 aB = *(const uint2*)(A2 + (t2 ^ sg2));   // {a2a3, a6a7}
            #pragma unroll
            for (int nt = 0; nt < 4; nt++) {
                uint2 bv = *(const uint2*)(Bb + nt * 8 * RWRD + 8 * k);
                mma16(d[nt], aA.x, aB.x, aA.y, aB.y, bv.x, bv.y);
            }
        }
    }
    __syncthreads();

    // ---- epilogue: bounce through smem as [o][p], coalesced STG.128 ----
    {
        #pragma unroll
        for (int nt = 0; nt < 4; nt++) {
            int ob = wn * 32 + nt * 8 + 2 * tig;
            int pb = wm * 16 + gid;
            Esf[ob * ESTRD + pb]           = d[nt][0];
            Esf[(ob + 1) * ESTRD + pb]     = d[nt][1];
            Esf[ob * ESTRD + pb + 8]       = d[nt][2];
            Esf[(ob + 1) * ESTRD + pb + 8] = d[nt][3];
        }
    }
    __syncthreads();
    {
        float* ob = out + (size_t)b * OO * HWSZ + (size_t)row * WW + j0;
        const int orow = tid >> 4;          // 0..31
        const int l4 = tid & 15;            // float4 index within 64-pixel row
        #pragma unroll
        for (int oo = 0; oo < 4; oo++) {
            int o = oo * 32 + orow;
            float4 v = *(const float4*)(Esf + o * ESTRD + l4 * 4);
            *(float4*)(ob + (size_t)o * HWSZ + l4 * 4) = v;
        }
    }
}

extern "C" void kernel_launch(void* const* d_in, const int* in_sizes, int n_in,
                              void* d_out, int out_size) {
    (void)in_sizes; (void)n_in; (void)out_size;
    const float* x     = (const float*)d_in[0];
    const float* theta = (const float*)d_in[1];
    const float* wdw   = (const float*)d_in[2];
    const float* wpw   = (const float*)d_in[3];
    float* out = (float*)d_out;

    prep_kernel<<<8, 512>>>(theta, wdw, wpw);
    cudaFuncSetAttribute(as2d_kernel, cudaFuncAttributeMaxDynamicSharedMemorySize, SM_TOTAL);
    as2d_kernel<<<BB * (HH * WW / MPIX), NTHREADS, SM_TOTAL>>>(x, out);
}

// round 11
// speedup vs baseline: 4.8024x; 1.0051x over previous
#include <cuda_runtime.h>
#include <cuda_fp16.h>
#include <stdint.h>

// ---------------- problem constants ----------------
#define BB 8
#define CC 128
#define HH 256
#define WW 256
#define OO 128
#define HWSZ (HH * WW)
#define NTHREADS 512

// A/B smem rows: 64 h2-words padded to 72
#define RWRD 72

// ---------------- smem layout (bytes) ----------------
#define SM_A   0                             // A: 128 x RWRD uint32 (36864 B); rows 0-63 reused as fp16 epilogue bounce
#define SM_B   (128 * RWRD * 4)              // B: 128 x RWRD uint32 (36864 B)
#define SM_W   (SM_B + 128 * RWRD * 4)       // row-masked weights float4[128]
#define SM_O   (SM_W + 2048)                 // int4 per channel {off0, off1, ifx, -}
#define SM_TOTAL (SM_O + 2048)               // 77824 B -> 2 CTAs/SM

// ---------------- precomputed globals (written by prep kernel) ----------------
__device__ float4   g_PW[CC];
__device__ int2     g_PI[CC];
__device__ uint32_t g_Bw[OO * 64];           // fp16x2 w_pw, pair-interleaved words

// pair-interleave: logical words w and w+4 land at adjacent positions
__host__ __device__ __forceinline__ int pairpos(int w) {
    return (w & ~7) + ((w & 3) << 1) + ((w >> 2) & 1);
}

__device__ __forceinline__ uint32_t packh2(float lo, float hi) {
    __half2 h = __floats2half2_rn(lo, hi);
    return *(uint32_t*)&h;
}

__device__ __forceinline__ void mma16(float* d, uint32_t a0, uint32_t a1, uint32_t a2,
                                      uint32_t a3, uint32_t b0, uint32_t b1) {
    asm volatile(
        "mma.sync.aligned.m16n8k16.row.col.f32.f16.f16.f32 "
        "{%0,%1,%2,%3}, {%4,%5,%6,%7}, {%8,%9}, {%0,%1,%2,%3};"
        : "+f"(d[0]), "+f"(d[1]), "+f"(d[2]), "+f"(d[3])
        : "r"(a0), "r"(a1), "r"(a2), "r"(a3), "r"(b0), "r"(b1));
}

// ---------------- prep kernel: params + fp16 pre-layout of w_pw ----------------
__global__ void prep_kernel(const float* __restrict__ theta, const float* __restrict__ wdw,
                            const float* __restrict__ wpw) {
    int t = blockIdx.x * blockDim.x + threadIdx.x;
    if (t < CC) {
        float ty = -theta[2 * t];
        float tx = -theta[2 * t + 1];
        float fy = floorf(ty), fx = floorf(tx);
        float dy = ty - fy, dx = tx - fx;
        float wd = wdw[t];
        g_PI[t] = make_int2((int)fy, (int)fx);
        g_PW[t] = make_float4((1.0f - dy) * (1.0f - dx) * wd,
                              (1.0f - dy) * dx * wd,
                              dy * (1.0f - dx) * wd,
                              dy * dx * wd);
    }
    if (t < OO * CC / 4) {                 // 4096 float4 chunks
        int o = t >> 5;
        int c4 = (t & 31) << 2;
        float4 v = ((const float4*)wpw)[t];
        int p0 = pairpos(c4 >> 1);
        g_Bw[o * 64 + p0]     = packh2(v.x, v.y);
        g_Bw[o * 64 + p0 + 2] = packh2(v.z, v.w);
    }
}

// ---------------- gather: both subtiles, one pass ----------------
// LO0=true:  subtile0 (cols j0a+p)      needs low-edge column guards, subtile1 interior
// LO0=false: subtile1 (cols j0a+64+p)   needs high-edge column guards, subtile0 interior
template<bool LO0>
__device__ __forceinline__ void gather_both(
    const float* __restrict__ xb, uint32_t* __restrict__ Asw,
    const float4* __restrict__ SW, const int4* __restrict__ SO,
    int p, int cs, int j0a)
{
    const int jj = cs & 3;
    const int g0 = (cs >> 2) << 2;
    const int sg = ((p >> 2) & 7) << 1;
    const int jA = j0a + p;
    const int jB = jA + 64;
    uint32_t* A0 = Asw + p * RWRD;
    uint32_t* A1 = Asw + (64 + p) * RWRD;

    #pragma unroll
    for (int q = 0; q < 4; q++) {
        const int g = g0 + q;
        const int c00 = 16 * g + 2 * jj;
        float sA[4], sB[4];
        #pragma unroll
        for (int cc = 0; cc < 4; cc++) {
            int c = c00 + (cc & 1) + ((cc & 2) ? 8 : 0);
            int4 off = SO[c];
            float4 wv = SW[c];
            const float* b0 = xb + off.x;
            const float* b1 = xb + off.y;
            float a00, a01, a10, a11;
            float c00v, c01v, c10v, c11v;
            if (LO0) {
                int qq = jA + off.z;
                bool ok0 = qq >= 0, ok1 = qq >= -1;
                a00 = ok0 ? b0[jA] : 0.0f;  a01 = ok1 ? b0[jA + 1] : 0.0f;
                a10 = ok0 ? b1[jA] : 0.0f;  a11 = ok1 ? b1[jA + 1] : 0.0f;
                c00v = b0[jB]; c01v = b0[jB + 1]; c10v = b1[jB]; c11v = b1[jB + 1];
            } else {
                a00 = b0[jA]; a01 = b0[jA + 1]; a10 = b1[jA]; a11 = b1[jA + 1];
                int qq = jB + off.z;
                bool ok0 = qq <= 255, ok1 = qq <= 254;
                c00v = ok0 ? b0[jB] : 0.0f;  c01v = ok1 ? b0[jB + 1] : 0.0f;
                c10v = ok0 ? b1[jB] : 0.0f;  c11v = ok1 ? b1[jB + 1] : 0.0f;
            }
            sA[cc] = a00 * wv.x + a01 * wv.y + a10 * wv.z + a11 * wv.w;
            sB[cc] = c00v * wv.x + c01v * wv.y + c10v * wv.z + c11v * wv.w;
        }
        const int pos = (8 * g + 2 * jj) ^ sg;
        *(uint2*)(A0 + pos) = make_uint2(packh2(sA[0], sA[1]), packh2(sA[2], sA[3]));
        *(uint2*)(A1 + pos) = make_uint2(packh2(sB[0], sB[1]), packh2(sB[2], sB[3]));
    }
}

// ---------------- main kernel ----------------
__global__ void __launch_bounds__(NTHREADS, 2)
as2d_kernel(const float* __restrict__ x, float* __restrict__ out) {
    extern __shared__ char smem[];
    const int tid = threadIdx.x;
    const int wid = tid >> 5;
    const int lid = tid & 31;
    const int gid = lid >> 2;
    const int tig = lid & 3;

    // pair tiles: 512 pairs per batch (256 rows x 2 half-rows of 128 px = 2 subtiles)
    const int blk = blockIdx.x;
    const int b = blk >> 9;
    const int rem = blk & 511;
    const int row = rem >> 1;
    const int pairid = rem & 1;
    const int j0a = pairid << 7;

    uint32_t* Asw = (uint32_t*)(smem + SM_A);
    uint32_t* Bsw = (uint32_t*)(smem + SM_B);
    float4*   SW  = (float4*)(smem + SM_W);
    int4*     SO  = (int4*)(smem + SM_O);

    // ---- per-CTA setup: row validity folded into weights, c*HWSZ folded into offsets ----
    if (tid < CC) {
        int2 iv = g_PI[tid];
        float4 w = g_PW[tid];
        int r0 = row + iv.x;
        int r1 = r0 + 1;
        bool rok0 = (unsigned)r0 < (unsigned)HH;
        bool rok1 = (unsigned)r1 < (unsigned)HH;
        int cr0 = min(max(r0, 0), HH - 1);
        int cr1 = min(max(r1, 0), HH - 1);
        SW[tid] = make_float4(rok0 ? w.x : 0.0f, rok0 ? w.y : 0.0f,
                              rok1 ? w.z : 0.0f, rok1 ? w.w : 0.0f);
        SO[tid] = make_int4(tid * HWSZ + cr0 * WW + iv.y,
                            tid * HWSZ + cr1 * WW + iv.y, iv.y, 0);
    }
    // ---- stage B tile (once per pair) ----
    #pragma unroll
    for (int i = 0; i < 4; i++) {
        int w4 = tid + i * NTHREADS;
        int r = w4 >> 4;
        int pos = (w4 & 15) << 2;
        uint4 v = ((const uint4*)g_Bw)[w4];
        *(uint4*)(Bsw + r * RWRD + pos) = v;
    }
    __syncthreads();

    // ---- gather both subtiles ----
    {
        const int p = tid & 63;
        const int cs = tid >> 6;
        const float* xb = x + (size_t)b * CC * HWSZ;
        if (pairid == 0)
            gather_both<true>(xb, Asw, SW, SO, p, cs, j0a);
        else
            gather_both<false>(xb, Asw, SW, SO, p, cs, j0a);
    }
    __syncthreads();

    // ---- two subtile GEMMs + epilogues ----
    const int wm = wid & 3;
    const int wn = wid >> 2;
    #pragma unroll
    for (int t = 0; t < 2; t++) {
        float d[4][4] = {};
        {
            const uint32_t* At = Asw + t * 64 * RWRD;
            const int r1 = wm * 16 + gid;
            const int r2 = r1 + 8;
            const int sg1 = ((r1 >> 2) & 7) << 1;
            const int sg2 = ((r2 >> 2) & 7) << 1;
            const uint32_t* A1 = At + r1 * RWRD;
            const uint32_t* A2 = At + r2 * RWRD;
            const uint32_t* Bb = Bsw + (wn * 32 + gid) * RWRD + 2 * tig;
            #pragma unroll
            for (int k = 0; k < 8; k++) {
                int t2 = 8 * k + 2 * tig;
                uint2 aA = *(const uint2*)(A1 + (t2 ^ sg1));
                uint2 aB = *(const uint2*)(A2 + (t2 ^ sg2));
                #pragma unroll
                for (int nt = 0; nt < 4; nt++) {
                    uint2 bv = *(const uint2*)(Bb + nt * 8 * RWRD + 8 * k);
                    mma16(d[nt], aA.x, aB.x, aA.y, aB.y, bv.x, bv.y);
                }
            }
        }
        __syncthreads();   // all warps done reading A rows 0-63 (t=0) / E2 free (t=1)

        // ---- epilogue STS: fp16 pairs along o into E2 (= A rows 0-63 region) ----
        {
            const int pb = wm * 16 + gid;
            #pragma unroll
            for (int nt = 0; nt < 4; nt++) {
                int o2 = wn * 16 + nt * 4 + tig;     // o-pair index (o = 2*o2, 2*o2+1)
                Asw[o2 * RWRD + pb]     = packh2(d[nt][0], d[nt][1]);
                Asw[o2 * RWRD + pb + 8] = packh2(d[nt][2], d[nt][3]);
            }
        }
        __syncthreads();

        // ---- epilogue out: each thread expands one o-pair x 4 px -> 2 coalesced STG.128 ----
        {
            const int o2a = tid >> 4;
            const int l4 = tid & 15;
            float* obase = out + (size_t)b * OO * HWSZ + (size_t)row * WW + j0a + t * 64 + 4 * l4;
            #pragma unroll
            for (int s2 = 0; s2 < 2; s2++) {
                int o2 = o2a + s2 * 32;
                uint4 v4 = *(const uint4*)(Asw + o2 * RWRD + 4 * l4);
                float2 f0 = __half22float2(*(__half2*)&v4.x);
                float2 f1 = __half22float2(*(__half2*)&v4.y);
                float2 f2 = __half22float2(*(__half2*)&v4.z);
                float2 f3 = __half22float2(*(__half2*)&v4.w);
                *(float4*)(obase + (size_t)(2 * o2) * HWSZ) =
                    make_float4(f0.x, f1.x, f2.x, f3.x);
                *(float4*)(obase + (size_t)(2 * o2 + 1) * HWSZ) =
                    make_float4(f0.y, f1.y, f2.y, f3.y);
            }
        }
        // no sync needed: next mainloop reads A rows 64-127 / B only;
        // its post-mainloop sync orders E2 reuse against these reads.
    }
}

extern "C" void kernel_launch(void* const* d_in, const int* in_sizes, int n_in,
                              void* d_out, int out_size) {
    (void)in_sizes; (void)n_in; (void)out_size;
    const float* x     = (const float*)d_in[0];
    const float* theta = (const float*)d_in[1];
    const float* wdw   = (const float*)d_in[2];
    const float* wpw   = (const float*)d_in[3];
    float* out = (float*)d_out;

    prep_kernel<<<8, 512>>>(theta, wdw, wpw);
    cudaFuncSetAttribute(as2d_kernel, cudaFuncAttributeMaxDynamicSharedMemorySize, SM_TOTAL);
    as2d_kernel<<<BB * (HH * WW / 128), NTHREADS, SM_TOTAL>>>(x, out);
}

// round 14
// speedup vs baseline: 4.8686x; 1.0138x over previous
#include <cuda_runtime.h>
#include <cuda_fp16.h>
#include <stdint.h>

// ---------------- problem constants ----------------
#define BB 8
#define CC 128
#define HH 256
#define WW 256
#define OO 128
#define HWSZ (HH * WW)
#define NTHREADS 512

// A/B smem rows: 64 h2-words padded to 72
#define RWRD 72

// ---------------- smem layout (bytes) ----------------
#define SM_A   0                             // A: 128 x RWRD uint32 (36864 B); rows 0-63 reused as fp16 epilogue bounce
#define SM_B   (128 * RWRD * 4)              // B: 128 x RWRD uint32 (36864 B)
#define SM_W   (SM_B + 128 * RWRD * 4)       // row-masked weights float4[128]
#define SM_O   (SM_W + 2048)                 // int4 per channel {off0, off1, ifx, -}
#define SM_TOTAL (SM_O + 2048)               // 77824 B -> 2 CTAs/SM

// ---------------- precomputed globals (written by prep kernel) ----------------
__device__ float4   g_PW[CC];
__device__ int2     g_PI[CC];
__device__ uint32_t g_Bw[OO * 64];           // fp16x2 w_pw, pair-interleaved words

// pair-interleave: logical words w and w+4 land at adjacent positions
__host__ __device__ __forceinline__ int pairpos(int w) {
    return (w & ~7) + ((w & 3) << 1) + ((w >> 2) & 1);
}

__device__ __forceinline__ uint32_t packh2(float lo, float hi) {
    __half2 h = __floats2half2_rn(lo, hi);
    return *(uint32_t*)&h;
}

__device__ __forceinline__ void mma16(float* d, uint32_t a0, uint32_t a1, uint32_t a2,
                                      uint32_t a3, uint32_t b0, uint32_t b1) {
    asm volatile(
        "mma.sync.aligned.m16n8k16.row.col.f32.f16.f16.f32 "
        "{%0,%1,%2,%3}, {%4,%5,%6,%7}, {%8,%9}, {%0,%1,%2,%3};"
        : "+f"(d[0]), "+f"(d[1]), "+f"(d[2]), "+f"(d[3])
        : "r"(a0), "r"(a1), "r"(a2), "r"(a3), "r"(b0), "r"(b1));
}

// ---------------- prep kernel: params + fp16 pre-layout of w_pw ----------------
__global__ void prep_kernel(const float* __restrict__ theta, const float* __restrict__ wdw,
                            const float* __restrict__ wpw) {
    int t = blockIdx.x * blockDim.x + threadIdx.x;
    if (t < CC) {
        float ty = -theta[2 * t];
        float tx = -theta[2 * t + 1];
        float fy = floorf(ty), fx = floorf(tx);
        float dy = ty - fy, dx = tx - fx;
        float wd = wdw[t];
        g_PI[t] = make_int2((int)fy, (int)fx);
        g_PW[t] = make_float4((1.0f - dy) * (1.0f - dx) * wd,
                              (1.0f - dy) * dx * wd,
                              dy * (1.0f - dx) * wd,
                              dy * dx * wd);
    }
    if (t < OO * CC / 4) {                 // 4096 float4 chunks
        int o = t >> 5;
        int c4 = (t & 31) << 2;
        float4 v = ((const float4*)wpw)[t];
        int p0 = pairpos(c4 >> 1);
        g_Bw[o * 64 + p0]     = packh2(v.x, v.y);
        g_Bw[o * 64 + p0 + 2] = packh2(v.z, v.w);
    }
}

// ---------------- gather: both subtiles, one pass ----------------
// LO0=true:  subtile0 (cols j0a+p)      needs low-edge column guards, subtile1 interior
// LO0=false: subtile1 (cols j0a+64+p)   needs high-edge column guards, subtile0 interior
template<bool LO0>
__device__ __forceinline__ void gather_both(
    const float* __restrict__ xb, uint32_t* __restrict__ Asw,
    const float4* __restrict__ SW, const int4* __restrict__ SO,
    int p, int cs, int j0a)
{
    const int jj = cs & 3;
    const int g0 = (cs >> 2) << 2;
    const int sg = ((p >> 2) & 7) << 1;
    const int jA = j0a + p;
    const int jB = jA + 64;
    uint32_t* A0 = Asw + p * RWRD;
    uint32_t* A1 = Asw + (64 + p) * RWRD;

    #pragma unroll
    for (int q = 0; q < 4; q++) {
        const int g = g0 + q;
        const int c00 = 16 * g + 2 * jj;
        float sA[4], sB[4];
        #pragma unroll
        for (int cc = 0; cc < 4; cc++) {
            int c = c00 + (cc & 1) + ((cc & 2) ? 8 : 0);
            int4 off = SO[c];
            float4 wv = SW[c];
            const float* b0 = xb + off.x;
            const float* b1 = xb + off.y;
            float a00, a01, a10, a11;
            float c00v, c01v, c10v, c11v;
            if (LO0) {
                int qq = jA + off.z;
                bool ok0 = qq >= 0, ok1 = qq >= -1;
                a00 = ok0 ? b0[jA] : 0.0f;  a01 = ok1 ? b0[jA + 1] : 0.0f;
                a10 = ok0 ? b1[jA] : 0.0f;  a11 = ok1 ? b1[jA + 1] : 0.0f;
                c00v = b0[jB]; c01v = b0[jB + 1]; c10v = b1[jB]; c11v = b1[jB + 1];
            } else {
                a00 = b0[jA]; a01 = b0[jA + 1]; a10 = b1[jA]; a11 = b1[jA + 1];
                int qq = jB + off.z;
                bool ok0 = qq <= 255, ok1 = qq <= 254;
                c00v = ok0 ? b0[jB] : 0.0f;  c01v = ok1 ? b0[jB + 1] : 0.0f;
                c10v = ok0 ? b1[jB] : 0.0f;  c11v = ok1 ? b1[jB + 1] : 0.0f;
            }
            sA[cc] = a00 * wv.x + a01 * wv.y + a10 * wv.z + a11 * wv.w;
            sB[cc] = c00v * wv.x + c01v * wv.y + c10v * wv.z + c11v * wv.w;
        }
        const int pos = (8 * g + 2 * jj) ^ sg;
        *(uint2*)(A0 + pos) = make_uint2(packh2(sA[0], sA[1]), packh2(sA[2], sA[3]));
        *(uint2*)(A1 + pos) = make_uint2(packh2(sB[0], sB[1]), packh2(sB[2], sB[3]));
    }
}

// ---------------- main kernel ----------------
__global__ void __launch_bounds__(NTHREADS, 2)
as2d_kernel(const float* __restrict__ x, float* __restrict__ out) {
    extern __shared__ char smem[];
    const int tid = threadIdx.x;
    const int wid = tid >> 5;
    const int lid = tid & 31;
    const int gid = lid >> 2;
    const int tig = lid & 3;

    // pair tiles: 512 pairs per batch (256 rows x 2 half-rows of 128 px = 2 subtiles)
    const int blk = blockIdx.x;
    const int b = blk >> 9;
    const int rem = blk & 511;
    const int row = rem >> 1;
    const int pairid = rem & 1;
    const int j0a = pairid << 7;

    uint32_t* Asw = (uint32_t*)(smem + SM_A);
    uint32_t* Bsw = (uint32_t*)(smem + SM_B);
    float4*   SW  = (float4*)(smem + SM_W);
    int4*     SO  = (int4*)(smem + SM_O);

    // ---- per-CTA setup: row validity folded into weights, c*HWSZ folded into offsets ----
    if (tid < CC) {
        int2 iv = g_PI[tid];
        float4 w = g_PW[tid];
        int r0 = row + iv.x;
        int r1 = r0 + 1;
        bool rok0 = (unsigned)r0 < (unsigned)HH;
        bool rok1 = (unsigned)r1 < (unsigned)HH;
        int cr0 = min(max(r0, 0), HH - 1);
        int cr1 = min(max(r1, 0), HH - 1);
        SW[tid] = make_float4(rok0 ? w.x : 0.0f, rok0 ? w.y : 0.0f,
                              rok1 ? w.z : 0.0f, rok1 ? w.w : 0.0f);
        SO[tid] = make_int4(tid * HWSZ + cr0 * WW + iv.y,
                            tid * HWSZ + cr1 * WW + iv.y, iv.y, 0);
    }
    // ---- stage B tile (once per pair) ----
    #pragma unroll
    for (int i = 0; i < 4; i++) {
        int w4 = tid + i * NTHREADS;
        int r = w4 >> 4;
        int pos = (w4 & 15) << 2;
        uint4 v = ((const uint4*)g_Bw)[w4];
        *(uint4*)(Bsw + r * RWRD + pos) = v;
    }
    __syncthreads();

    // ---- gather both subtiles ----
    {
        const int p = tid & 63;
        const int cs = tid >> 6;
        const float* xb = x + (size_t)b * CC * HWSZ;
        if (pairid == 0)
            gather_both<true>(xb, Asw, SW, SO, p, cs, j0a);
        else
            gather_both<false>(xb, Asw, SW, SO, p, cs, j0a);
    }
    __syncthreads();

    // ---- two subtile GEMMs + epilogues ----
    const int wm = wid & 3;
    const int wn = wid >> 2;
    #pragma unroll
    for (int t = 0; t < 2; t++) {
        float d[4][4] = {};
        {
            const uint32_t* At = Asw + t * 64 * RWRD;
            const int r1 = wm * 16 + gid;
            const int r2 = r1 + 8;
            const int sg1 = ((r1 >> 2) & 7) << 1;
            const int sg2 = ((r2 >> 2) & 7) << 1;
            const uint32_t* A1 = At + r1 * RWRD;
            const uint32_t* A2 = At + r2 * RWRD;
            const uint32_t* Bb = Bsw + (wn * 32 + gid) * RWRD + 2 * tig;
            #pragma unroll
            for (int k = 0; k < 8; k++) {
                int t2 = 8 * k + 2 * tig;
                uint2 aA = *(const uint2*)(A1 + (t2 ^ sg1));
                uint2 aB = *(const uint2*)(A2 + (t2 ^ sg2));
                #pragma unroll
                for (int nt = 0; nt < 4; nt++) {
                    uint2 bv = *(const uint2*)(Bb + nt * 8 * RWRD + 8 * k);
                    mma16(d[nt], aA.x, aB.x, aA.y, aB.y, bv.x, bv.y);
                }
            }
        }
        __syncthreads();   // all warps done reading A rows 0-63 (t=0) / E2 free (t=1)

        // ---- epilogue STS: fp16 pairs along o into E2 (= A rows 0-63 region) ----
        {
            const int pb = wm * 16 + gid;
            #pragma unroll
            for (int nt = 0; nt < 4; nt++) {
                int o2 = wn * 16 + nt * 4 + tig;     // o-pair index (o = 2*o2, 2*o2+1)
                Asw[o2 * RWRD + pb]     = packh2(d[nt][0], d[nt][1]);
                Asw[o2 * RWRD + pb + 8] = packh2(d[nt][2], d[nt][3]);
            }
        }
        __syncthreads();

        // ---- epilogue out: each thread expands one o-pair x 4 px -> 2 coalesced STG.128 ----
        {
            const int o2a = tid >> 4;
            const int l4 = tid & 15;
            float* obase = out + (size_t)b * OO * HWSZ + (size_t)row * WW + j0a + t * 64 + 4 * l4;
            #pragma unroll
            for (int s2 = 0; s2 < 2; s2++) {
                int o2 = o2a + s2 * 32;
                uint4 v4 = *(const uint4*)(Asw + o2 * RWRD + 4 * l4);
                float2 f0 = __half22float2(*(__half2*)&v4.x);
                float2 f1 = __half22float2(*(__half2*)&v4.y);
                float2 f2 = __half22float2(*(__half2*)&v4.z);
                float2 f3 = __half22float2(*(__half2*)&v4.w);
                *(float4*)(obase + (size_t)(2 * o2) * HWSZ) =
                    make_float4(f0.x, f1.x, f2.x, f3.x);
                *(float4*)(obase + (size_t)(2 * o2 + 1) * HWSZ) =
                    make_float4(f0.y, f1.y, f2.y, f3.y);
            }
        }
        // no sync needed: next mainloop reads A rows 64-127 / B only;
        // its post-mainloop sync orders E2 reuse against these reads.
    }
}

extern "C" void kernel_launch(void* const* d_in, const int* in_sizes, int n_in,
                              void* d_out, int out_size) {
    (void)in_sizes; (void)n_in; (void)out_size;
    const float* x     = (const float*)d_in[0];
    const float* theta = (const float*)d_in[1];
    const float* wdw   = (const float*)d_in[2];
    const float* wpw   = (const float*)d_in[3];
    float* out = (float*)d_out;

    prep_kernel<<<8, 512>>>(theta, wdw, wpw);
    cudaFuncSetAttribute(as2d_kernel, cudaFuncAttributeMaxDynamicSharedMemorySize, SM_TOTAL);
    as2d_kernel<<<BB * (HH * WW / 128), NTHREADS, SM_TOTAL>>>(x, out);
}

// round 15
// speedup vs baseline: 4.8723x; 1.0008x over previous
#include <cuda_runtime.h>
#include <cuda_fp16.h>
#include <stdint.h>

// ---------------- problem constants ----------------
#define BB 8
#define CC 128
#define HH 256
#define WW 256
#define OO 128
#define HWSZ (HH * WW)
#define NTHREADS 512

// A/B smem rows: 64 h2-words padded to 72
#define RWRD 72

// ---------------- smem layout (bytes) ----------------
#define SM_A   0                             // A: 128 x RWRD uint32 (36864 B); rows 0-63 reused as fp16 epilogue bounce
#define SM_B   (128 * RWRD * 4)              // B: 128 x RWRD uint32 (36864 B)
#define SM_W   (SM_B + 128 * RWRD * 4)       // row-masked weights float4[128]
#define SM_O   (SM_W + 2048)                 // int4 per channel {off0, off1, ifx, -}
#define SM_TOTAL (SM_O + 2048)               // 77824 B -> 2 CTAs/SM

// ---------------- precomputed globals (written by prep kernel) ----------------
__device__ float4   g_PW[CC];
__device__ int2     g_PI[CC];
__device__ uint32_t g_Bw[OO * 64];           // fp16x2 w_pw, pair-interleaved words

// pair-interleave: logical words w and w+4 land at adjacent positions
__host__ __device__ __forceinline__ int pairpos(int w) {
    return (w & ~7) + ((w & 3) << 1) + ((w >> 2) & 1);
}

__device__ __forceinline__ uint32_t packh2(float lo, float hi) {
    __half2 h = __floats2half2_rn(lo, hi);
    return *(uint32_t*)&h;
}

__device__ __forceinline__ void mma16(float* d, uint32_t a0, uint32_t a1, uint32_t a2,
                                      uint32_t a3, uint32_t b0, uint32_t b1) {
    asm volatile(
        "mma.sync.aligned.m16n8k16.row.col.f32.f16.f16.f32 "
        "{%0,%1,%2,%3}, {%4,%5,%6,%7}, {%8,%9}, {%0,%1,%2,%3};"
        : "+f"(d[0]), "+f"(d[1]), "+f"(d[2]), "+f"(d[3])
        : "r"(a0), "r"(a1), "r"(a2), "r"(a3), "r"(b0), "r"(b1));
}

// ---------------- prep kernel: params + fp16 pre-layout of w_pw ----------------
__global__ void prep_kernel(const float* __restrict__ theta, const float* __restrict__ wdw,
                            const float* __restrict__ wpw) {
    int t = blockIdx.x * blockDim.x + threadIdx.x;
    if (t < CC) {
        float ty = -theta[2 * t];
        float tx = -theta[2 * t + 1];
        float fy = floorf(ty), fx = floorf(tx);
        float dy = ty - fy, dx = tx - fx;
        float wd = wdw[t];
        g_PI[t] = make_int2((int)fy, (int)fx);
        g_PW[t] = make_float4((1.0f - dy) * (1.0f - dx) * wd,
                              (1.0f - dy) * dx * wd,
                              dy * (1.0f - dx) * wd,
                              dy * dx * wd);
    }
    if (t < OO * CC / 4) {                 // 4096 float4 chunks
        int o = t >> 5;
        int c4 = (t & 31) << 2;
        float4 v = ((const float4*)wpw)[t];
        int p0 = pairpos(c4 >> 1);
        g_Bw[o * 64 + p0]     = packh2(v.x, v.y);
        g_Bw[o * 64 + p0 + 2] = packh2(v.z, v.w);
    }
}

// ---------------- gather: both subtiles, one pass ----------------
// LO0=true:  subtile0 (cols j0a+p)      needs low-edge column guards, subtile1 interior
// LO0=false: subtile1 (cols j0a+64+p)   needs high-edge column guards, subtile0 interior
template<bool LO0>
__device__ __forceinline__ void gather_both(
    const float* __restrict__ xb, uint32_t* __restrict__ Asw,
    const float4* __restrict__ SW, const int4* __restrict__ SO,
    int p, int cs, int j0a)
{
    const int jj = cs & 3;
    const int g0 = (cs >> 2) << 2;
    const int sg = ((p >> 2) & 7) << 1;
    const int jA = j0a + p;
    const int jB = jA + 64;
    uint32_t* A0 = Asw + p * RWRD;
    uint32_t* A1 = Asw + (64 + p) * RWRD;

    #pragma unroll
    for (int q = 0; q < 4; q++) {
        const int g = g0 + q;
        const int c00 = 16 * g + 2 * jj;
        float sA[4], sB[4];
        #pragma unroll
        for (int cc = 0; cc < 4; cc++) {
            int c = c00 + (cc & 1) + ((cc & 2) ? 8 : 0);
            int4 off = SO[c];
            float4 wv = SW[c];
            const float* b0 = xb + off.x;
            const float* b1 = xb + off.y;
            float a00, a01, a10, a11;
            float c00v, c01v, c10v, c11v;
            if (LO0) {
                int qq = jA + off.z;
                bool ok0 = qq >= 0, ok1 = qq >= -1;
                a00 = ok0 ? b0[jA] : 0.0f;  a01 = ok1 ? b0[jA + 1] : 0.0f;
                a10 = ok0 ? b1[jA] : 0.0f;  a11 = ok1 ? b1[jA + 1] : 0.0f;
                c00v = b0[jB]; c01v = b0[jB + 1]; c10v = b1[jB]; c11v = b1[jB + 1];
            } else {
                a00 = b0[jA]; a01 = b0[jA + 1]; a10 = b1[jA]; a11 = b1[jA + 1];
                int qq = jB + off.z;
                bool ok0 = qq <= 255, ok1 = qq <= 254;
                c00v = ok0 ? b0[jB] : 0.0f;  c01v = ok1 ? b0[jB + 1] : 0.0f;
                c10v = ok0 ? b1[jB] : 0.0f;  c11v = ok1 ? b1[jB + 1] : 0.0f;
            }
            sA[cc] = a00 * wv.x + a01 * wv.y + a10 * wv.z + a11 * wv.w;
            sB[cc] = c00v * wv.x + c01v * wv.y + c10v * wv.z + c11v * wv.w;
        }
        const int pos = (8 * g + 2 * jj) ^ sg;
        *(uint2*)(A0 + pos) = make_uint2(packh2(sA[0], sA[1]), packh2(sA[2], sA[3]));
        *(uint2*)(A1 + pos) = make_uint2(packh2(sB[0], sB[1]), packh2(sB[2], sB[3]));
    }
}

// ---------------- main kernel ----------------
__global__ void __launch_bounds__(NTHREADS, 2)
as2d_kernel(const float* __restrict__ x, float* __restrict__ out) {
    extern __shared__ char smem[];
    const int tid = threadIdx.x;
    const int wid = tid >> 5;
    const int lid = tid & 31;
    const int gid = lid >> 2;
    const int tig = lid & 3;

    // pair tiles: 512 pairs per batch (256 rows x 2 half-rows of 128 px = 2 subtiles)
    const int blk = blockIdx.x;
    const int b = blk >> 9;
    const int rem = blk & 511;
    const int row = rem >> 1;
    const int pairid = rem & 1;
    const int j0a = pairid << 7;

    uint32_t* Asw = (uint32_t*)(smem + SM_A);
    uint32_t* Bsw = (uint32_t*)(smem + SM_B);
    float4*   SW  = (float4*)(smem + SM_W);
    int4*     SO  = (int4*)(smem + SM_O);

    // ---- per-CTA setup: row validity folded into weights, c*HWSZ folded into offsets ----
    if (tid < CC) {
        int2 iv = g_PI[tid];
        float4 w = g_PW[tid];
        int r0 = row + iv.x;
        int r1 = r0 + 1;
        bool rok0 = (unsigned)r0 < (unsigned)HH;
        bool rok1 = (unsigned)r1 < (unsigned)HH;
        int cr0 = min(max(r0, 0), HH - 1);
        int cr1 = min(max(r1, 0), HH - 1);
        SW[tid] = make_float4(rok0 ? w.x : 0.0f, rok0 ? w.y : 0.0f,
                              rok1 ? w.z : 0.0f, rok1 ? w.w : 0.0f);
        SO[tid] = make_int4(tid * HWSZ + cr0 * WW + iv.y,
                            tid * HWSZ + cr1 * WW + iv.y, iv.y, 0);
    }
    // ---- stage B tile (once per pair) ----
    #pragma unroll
    for (int i = 0; i < 4; i++) {
        int w4 = tid + i * NTHREADS;
        int r = w4 >> 4;
        int pos = (w4 & 15) << 2;
        uint4 v = ((const uint4*)g_Bw)[w4];
        *(uint4*)(Bsw + r * RWRD + pos) = v;
    }
    __syncthreads();

    // ---- gather both subtiles ----
    {
        const int p = tid & 63;
        const int cs = tid >> 6;
        const float* xb = x + (size_t)b * CC * HWSZ;
        if (pairid == 0)
            gather_both<true>(xb, Asw, SW, SO, p, cs, j0a);
        else
            gather_both<false>(xb, Asw, SW, SO, p, cs, j0a);
    }
    __syncthreads();

    // ---- two subtile GEMMs + epilogues ----
    const int wm = wid & 3;
    const int wn = wid >> 2;
    #pragma unroll
    for (int t = 0; t < 2; t++) {
        float d[4][4] = {};
        {
            const uint32_t* At = Asw + t * 64 * RWRD;
            const int r1 = wm * 16 + gid;
            const int r2 = r1 + 8;
            const int sg1 = ((r1 >> 2) & 7) << 1;
            const int sg2 = ((r2 >> 2) & 7) << 1;
            const uint32_t* A1 = At + r1 * RWRD;
            const uint32_t* A2 = At + r2 * RWRD;
            const uint32_t* Bb = Bsw + (wn * 32 + gid) * RWRD + 2 * tig;
            #pragma unroll
            for (int k = 0; k < 8; k++) {
                int t2 = 8 * k + 2 * tig;
                uint2 aA = *(const uint2*)(A1 + (t2 ^ sg1));
                uint2 aB = *(const uint2*)(A2 + (t2 ^ sg2));
                #pragma unroll
                for (int nt = 0; nt < 4; nt++) {
                    uint2 bv = *(const uint2*)(Bb + nt * 8 * RWRD + 8 * k);
                    mma16(d[nt], aA.x, aB.x, aA.y, aB.y, bv.x, bv.y);
                }
            }
        }
        __syncthreads();   // all warps done reading A rows 0-63 (t=0) / E2 free (t=1)

        // ---- epilogue STS: fp16 pairs along o into E2 (= A rows 0-63 region) ----
        {
            const int pb = wm * 16 + gid;
            #pragma unroll
            for (int nt = 0; nt < 4; nt++) {
                int o2 = wn * 16 + nt * 4 + tig;     // o-pair index (o = 2*o2, 2*o2+1)
                Asw[o2 * RWRD + pb]     = packh2(d[nt][0], d[nt][1]);
                Asw[o2 * RWRD + pb + 8] = packh2(d[nt][2], d[nt][3]);
            }
        }
        __syncthreads();

        // ---- epilogue out: each thread expands one o-pair x 4 px -> 2 coalesced STG.128 ----
        {
            const int o2a = tid >> 4;
            const int l4 = tid & 15;
            float* obase = out + (size_t)b * OO * HWSZ + (size_t)row * WW + j0a + t * 64 + 4 * l4;
            #pragma unroll
            for (int s2 = 0; s2 < 2; s2++) {
                int o2 = o2a + s2 * 32;
                uint4 v4 = *(const uint4*)(Asw + o2 * RWRD + 4 * l4);
                float2 f0 = __half22float2(*(__half2*)&v4.x);
                float2 f1 = __half22float2(*(__half2*)&v4.y);
                float2 f2 = __half22float2(*(__half2*)&v4.z);
                float2 f3 = __half22float2(*(__half2*)&v4.w);
                *(float4*)(obase + (size_t)(2 * o2) * HWSZ) =
                    make_float4(f0.x, f1.x, f2.x, f3.x);
                *(float4*)(obase + (size_t)(2 * o2 + 1) * HWSZ) =
                    make_float4(f0.y, f1.y, f2.y, f3.y);
            }
        }
        // no sync needed: next mainloop reads A rows 64-127 / B only;
        // its post-mainloop sync orders E2 reuse against these reads.
    }
}

extern "C" void kernel_launch(void* const* d_in, const int* in_sizes, int n_in,
                              void* d_out, int out_size) {
    (void)in_sizes; (void)n_in; (void)out_size;
    const float* x     = (const float*)d_in[0];
    const float* theta = (const float*)d_in[1];
    const float* wdw   = (const float*)d_in[2];
    const float* wpw   = (const float*)d_in[3];
    float* out = (float*)d_out;

    prep_kernel<<<8, 512>>>(theta, wdw, wpw);
    cudaFuncSetAttribute(as2d_kernel, cudaFuncAttributeMaxDynamicSharedMemorySize, SM_TOTAL);
    as2d_kernel<<<BB * (HH * WW / 128), NTHREADS, SM_TOTAL>>>(x, out);
}